// round 10
// baseline (speedup 1.0000x reference)
#include <cuda_runtime.h>
#include <math.h>

// Input order (metadata): 0:N 1:Zf 2:rij 3:cutoff_values 4:idx_i 5:idx_j
//                         6:adiv 7:apow 8:c1 9:c2 10:c3 11:c4 12:a1 13:a2 14:a3 15:a4
// Output: float[N]

#define KEHALF 7.199822675975274f

struct ZParams {
    float sp_adiv, sp_apow;
    float c1n, c2n, c3n, c4n;
    float s1, s2, s3, s4;
};

// Fast float softplus (scalar prep; exactness irrelevant at 1e-3 tolerance).
static __device__ __forceinline__ float sp_f(float x) {
    return log1pf(__expf(x));
}

// Per-block parameter computation: warp 0 lanes 0..9 each softplus one scalar,
// lane 0 assembles the normalized struct into smem. ~100 cycles per block,
// removes the serial prep-kernel launch entirely.
__device__ __forceinline__ void compute_params(const float* const* srcs,
                                               ZParams* s_p) {
    if (threadIdx.x < 32) {
        int lane = threadIdx.x;
        float v = 0.0f;
        if (lane < 10) v = sp_f(srcs[lane][0]);
        float sp_adiv = __shfl_sync(0xffffffffu, v, 0);
        float sp_apow = __shfl_sync(0xffffffffu, v, 1);
        float c1p     = __shfl_sync(0xffffffffu, v, 2);
        float c2p     = __shfl_sync(0xffffffffu, v, 3);
        float c3p     = __shfl_sync(0xffffffffu, v, 4);
        float c4p     = __shfl_sync(0xffffffffu, v, 5);
        float s1      = __shfl_sync(0xffffffffu, v, 6);
        float s2      = __shfl_sync(0xffffffffu, v, 7);
        float s3      = __shfl_sync(0xffffffffu, v, 8);
        float s4      = __shfl_sync(0xffffffffu, v, 9);
        if (lane == 0) {
            float inv = 1.0f / (c1p + c2p + c3p + c4p);
            s_p->sp_adiv = sp_adiv;
            s_p->sp_apow = sp_apow;
            s_p->c1n = c1p * inv;
            s_p->c2n = c2p * inv;
            s_p->c3n = c3p * inv;
            s_p->c4n = c4p * inv;
            s_p->s1 = s1; s_p->s2 = s2; s_p->s3 = s3; s_p->s4 = s4;
        }
    }
    __syncthreads();
}

__device__ __forceinline__ float zbl_pair(const ZParams& p,
                                          float Zi, float Zj,
                                          float r, float cut) {
    // z = Z^sp(apow)  -> MUFU.LG2 + FMUL + MUFU.EX2
    float zi = __powf(Zi, p.sp_apow);
    float zj = __powf(Zj, p.sp_apow);
    float a  = (zi + zj) * p.sp_adiv;
    float ar = a * r;
    float f = p.c1n * __expf(-p.s1 * ar)
            + p.c2n * __expf(-p.s2 * ar)
            + p.c3n * __expf(-p.s3 * ar)
            + p.c4n * __expf(-p.s4 * ar);
    float zizj = Zi * Zj;
    return __fdividef(KEHALF * f * cut * zizj, r);
}

__global__ void __launch_bounds__(256)
zbl_pair_kernel4(const float* __restrict__ Zf,
                 const float4* __restrict__ rij4,
                 const float4* __restrict__ cut4,
                 const int4* __restrict__ ii4,
                 const int4* __restrict__ jj4,
                 float* __restrict__ out,
                 int n4,
                 const float* adiv, const float* apow,
                 const float* c1, const float* c2,
                 const float* c3, const float* c4,
                 const float* a1, const float* a2,
                 const float* a3, const float* a4) {
    __shared__ ZParams s_p;
    {
        const float* srcs[10] = {adiv, apow, c1, c2, c3, c4, a1, a2, a3, a4};
        compute_params(srcs, &s_p);
    }

    int t = blockIdx.x * blockDim.x + threadIdx.x;
    if (t >= n4) return;

    ZParams p = s_p;

    // Streaming reads: evict-first so they don't pollute L1/L2 for the gathers
    float4 r  = __ldcs(&rij4[t]);
    float4 c  = __ldcs(&cut4[t]);
    int4   ii = __ldcs(&ii4[t]);
    int4   jj = __ldcs(&jj4[t]);

    int ia[4] = {ii.x, ii.y, ii.z, ii.w};
    int ja[4] = {jj.x, jj.y, jj.z, jj.w};
    float rr[4] = {r.x, r.y, r.z, r.w};
    float cc[4] = {c.x, c.y, c.z, c.w};

    // Batch the 8 random gathers first for maximum MLP
    float Zi[4], Zj[4];
#pragma unroll
    for (int k = 0; k < 4; k++) {
        Zi[k] = __ldg(Zf + ia[k]);
        Zj[k] = __ldg(Zf + ja[k]);
    }

    float contrib[4];
#pragma unroll
    for (int k = 0; k < 4; k++) {
        contrib[k] = zbl_pair(p, Zi[k], Zj[k], rr[k], cc[k]);
    }

#pragma unroll
    for (int k = 0; k < 4; k++) {
        atomicAdd(out + ia[k], contrib[k]);
    }
}

__global__ void zbl_pair_tail(const float* __restrict__ Zf,
                              const float* __restrict__ rij,
                              const float* __restrict__ cut,
                              const int* __restrict__ idx_i,
                              const int* __restrict__ idx_j,
                              float* __restrict__ out,
                              int start, int n,
                              const float* adiv, const float* apow,
                              const float* c1, const float* c2,
                              const float* c3, const float* c4,
                              const float* a1, const float* a2,
                              const float* a3, const float* a4) {
    __shared__ ZParams s_p;
    {
        const float* srcs[10] = {adiv, apow, c1, c2, c3, c4, a1, a2, a3, a4};
        compute_params(srcs, &s_p);
    }
    int t = start + blockIdx.x * blockDim.x + threadIdx.x;
    if (t >= n) return;
    float contrib = zbl_pair(s_p, __ldg(Zf + idx_i[t]), __ldg(Zf + idx_j[t]),
                             rij[t], cut[t]);
    atomicAdd(out + idx_i[t], contrib);
}

extern "C" void kernel_launch(void* const* d_in, const int* in_sizes, int n_in,
                              void* d_out, int out_size) {
    const float* Zf    = (const float*)d_in[1];
    const float* rij   = (const float*)d_in[2];
    const float* cut   = (const float*)d_in[3];
    const int*   idx_i = (const int*)d_in[4];
    const int*   idx_j = (const int*)d_in[5];
    const float* adiv  = (const float*)d_in[6];
    const float* apow  = (const float*)d_in[7];
    const float* c1    = (const float*)d_in[8];
    const float* c2    = (const float*)d_in[9];
    const float* c3    = (const float*)d_in[10];
    const float* c4    = (const float*)d_in[11];
    const float* a1    = (const float*)d_in[12];
    const float* a2    = (const float*)d_in[13];
    const float* a3    = (const float*)d_in[14];
    const float* a4    = (const float*)d_in[15];
    float* out = (float*)d_out;

    int n_pairs = in_sizes[2];

    // 1) zero the poisoned output (accumulator semantics per replay)
    cudaMemsetAsync(d_out, 0, (size_t)out_size * sizeof(float), 0);

    // 2) main pair sweep, 4 pairs per thread; params computed per block
    int n4 = n_pairs / 4;
    if (n4 > 0) {
        int threads = 256;
        int blocks = (n4 + threads - 1) / threads;
        zbl_pair_kernel4<<<blocks, threads>>>(
            Zf, (const float4*)rij, (const float4*)cut,
            (const int4*)idx_i, (const int4*)idx_j, out, n4,
            adiv, apow, c1, c2, c3, c4, a1, a2, a3, a4);
    }

    // 3) tail (n_pairs not divisible by 4)
    int done = n4 * 4;
    int rem = n_pairs - done;
    if (rem > 0) {
        zbl_pair_tail<<<(rem + 255) / 256, 256>>>(
            Zf, rij, cut, idx_i, idx_j, out, done, n_pairs,
            adiv, apow, c1, c2, c3, c4, a1, a2, a3, a4);
    }
}

// round 13
// speedup vs baseline: 1.1945x; 1.1945x over previous
#include <cuda_runtime.h>
#include <math.h>

// Input order (metadata): 0:N 1:Zf 2:rij 3:cutoff_values 4:idx_i 5:idx_j
//                         6:adiv 7:apow 8:c1 9:c2 10:c3 11:c4 12:a1 13:a2 14:a3 15:a4
// Output: float[N]

#define KEHALF 7.199822675975274f

struct ZParams {
    float sp_adiv, sp_apow;
    float c1n, c2n, c3n, c4n;
    float s1, s2, s3, s4;
};

__device__ ZParams g_p;

// Fast float softplus (one-time scalar prep; exactness irrelevant at 1e-3 tol).
static __device__ __forceinline__ float sp_f(float x) {
    return log1pf(__expf(x));
}

// Fused: zero the output array (grid-stride float4) AND compute the derived
// scalar parameters (block 0, warp 0, parallel lanes). One launch instead of
// memset + prep kernel.
__global__ void zbl_zero_prep_kernel(float4* __restrict__ out4, int n4,
                                     float* __restrict__ out_tail, int tail_lo, int tail_hi,
                                     const float* adiv, const float* apow,
                                     const float* c1, const float* c2,
                                     const float* c3, const float* c4,
                                     const float* a1, const float* a2,
                                     const float* a3, const float* a4) {
    // params: block 0, warp 0
    if (blockIdx.x == 0 && threadIdx.x < 32) {
        int lane = threadIdx.x;
        const float* srcs[10] = {adiv, apow, c1, c2, c3, c4, a1, a2, a3, a4};
        float v = 0.0f;
        if (lane < 10) v = sp_f(srcs[lane][0]);
        float sp_adiv = __shfl_sync(0xffffffffu, v, 0);
        float sp_apow = __shfl_sync(0xffffffffu, v, 1);
        float c1p     = __shfl_sync(0xffffffffu, v, 2);
        float c2p     = __shfl_sync(0xffffffffu, v, 3);
        float c3p     = __shfl_sync(0xffffffffu, v, 4);
        float c4p     = __shfl_sync(0xffffffffu, v, 5);
        float s1      = __shfl_sync(0xffffffffu, v, 6);
        float s2      = __shfl_sync(0xffffffffu, v, 7);
        float s3      = __shfl_sync(0xffffffffu, v, 8);
        float s4      = __shfl_sync(0xffffffffu, v, 9);
        if (lane == 0) {
            float inv = 1.0f / (c1p + c2p + c3p + c4p);
            ZParams p;
            p.sp_adiv = sp_adiv;
            p.sp_apow = sp_apow;
            p.c1n = c1p * inv;
            p.c2n = c2p * inv;
            p.c3n = c3p * inv;
            p.c4n = c4p * inv;
            p.s1 = s1; p.s2 = s2; p.s3 = s3; p.s4 = s4;
            g_p = p;
        }
    }
    // zero
    const float4 z4 = make_float4(0.f, 0.f, 0.f, 0.f);
    for (int i = blockIdx.x * blockDim.x + threadIdx.x; i < n4;
         i += gridDim.x * blockDim.x) {
        out4[i] = z4;
    }
    // scalar tail of the zero (if out_size % 4 != 0)
    int t = tail_lo + blockIdx.x * blockDim.x + threadIdx.x;
    if (t < tail_hi) out_tail[t] = 0.0f;
}

__device__ __forceinline__ float zbl_pair(const ZParams& p,
                                          float Zi, float Zj,
                                          float r, float cut) {
    // z = Z^sp(apow)  -> MUFU.LG2 + FMUL + MUFU.EX2
    float zi = __powf(Zi, p.sp_apow);
    float zj = __powf(Zj, p.sp_apow);
    float a  = (zi + zj) * p.sp_adiv;
    float ar = a * r;
    float f = p.c1n * __expf(-p.s1 * ar)
            + p.c2n * __expf(-p.s2 * ar)
            + p.c3n * __expf(-p.s3 * ar)
            + p.c4n * __expf(-p.s4 * ar);
    float zizj = Zi * Zj;
    return __fdividef(KEHALF * f * cut * zizj, r);
}

__global__ void __launch_bounds__(256)
zbl_pair_kernel4(const float* __restrict__ Zf,
                 const float4* __restrict__ rij4,
                 const float4* __restrict__ cut4,
                 const int4* __restrict__ ii4,
                 const int4* __restrict__ jj4,
                 float* __restrict__ out,
                 int n4) {
    int t = blockIdx.x * blockDim.x + threadIdx.x;
    if (t >= n4) return;

    ZParams p = g_p;

    float4 r  = __ldg(&rij4[t]);
    float4 c  = __ldg(&cut4[t]);
    int4   ii = __ldg(&ii4[t]);
    int4   jj = __ldg(&jj4[t]);

    int ia[4] = {ii.x, ii.y, ii.z, ii.w};
    int ja[4] = {jj.x, jj.y, jj.z, jj.w};
    float rr[4] = {r.x, r.y, r.z, r.w};
    float cc[4] = {c.x, c.y, c.z, c.w};

    // Batch the 8 random gathers first for maximum MLP
    float Zi[4], Zj[4];
#pragma unroll
    for (int k = 0; k < 4; k++) {
        Zi[k] = __ldg(Zf + ia[k]);
        Zj[k] = __ldg(Zf + ja[k]);
    }

    float contrib[4];
#pragma unroll
    for (int k = 0; k < 4; k++) {
        contrib[k] = zbl_pair(p, Zi[k], Zj[k], rr[k], cc[k]);
    }

#pragma unroll
    for (int k = 0; k < 4; k++) {
        atomicAdd(out + ia[k], contrib[k]);
    }
}

__global__ void zbl_pair_tail(const float* __restrict__ Zf,
                              const float* __restrict__ rij,
                              const float* __restrict__ cut,
                              const int* __restrict__ idx_i,
                              const int* __restrict__ idx_j,
                              float* __restrict__ out,
                              int start, int n) {
    int t = start + blockIdx.x * blockDim.x + threadIdx.x;
    if (t >= n) return;
    ZParams p = g_p;
    float contrib = zbl_pair(p, __ldg(Zf + idx_i[t]), __ldg(Zf + idx_j[t]),
                             rij[t], cut[t]);
    atomicAdd(out + idx_i[t], contrib);
}

extern "C" void kernel_launch(void* const* d_in, const int* in_sizes, int n_in,
                              void* d_out, int out_size) {
    const float* Zf    = (const float*)d_in[1];
    const float* rij   = (const float*)d_in[2];
    const float* cut   = (const float*)d_in[3];
    const int*   idx_i = (const int*)d_in[4];
    const int*   idx_j = (const int*)d_in[5];
    const float* adiv  = (const float*)d_in[6];
    const float* apow  = (const float*)d_in[7];
    const float* c1    = (const float*)d_in[8];
    const float* c2    = (const float*)d_in[9];
    const float* c3    = (const float*)d_in[10];
    const float* c4    = (const float*)d_in[11];
    const float* a1    = (const float*)d_in[12];
    const float* a2    = (const float*)d_in[13];
    const float* a3    = (const float*)d_in[14];
    const float* a4    = (const float*)d_in[15];
    float* out = (float*)d_out;

    int n_pairs = in_sizes[2];

    // 1) fused zero + scalar prep (single launch)
    int o4 = out_size / 4;
    int tail_lo = o4 * 4;
    {
        int threads = 256;
        int blocks = (o4 + threads - 1) / threads;
        if (blocks < 1) blocks = 1;
        if (blocks > 1024) blocks = 1024;
        zbl_zero_prep_kernel<<<blocks, threads>>>(
            (float4*)out, o4, out, tail_lo, out_size,
            adiv, apow, c1, c2, c3, c4, a1, a2, a3, a4);
    }

    // 2) main pair sweep, 4 pairs per thread
    int n4 = n_pairs / 4;
    if (n4 > 0) {
        int threads = 256;
        int blocks = (n4 + threads - 1) / threads;
        zbl_pair_kernel4<<<blocks, threads>>>(
            Zf, (const float4*)rij, (const float4*)cut,
            (const int4*)idx_i, (const int4*)idx_j, out, n4);
    }

    // 3) tail (n_pairs not divisible by 4)
    int done = n4 * 4;
    int rem = n_pairs - done;
    if (rem > 0) {
        zbl_pair_tail<<<(rem + 255) / 256, 256>>>(
            Zf, rij, cut, idx_i, idx_j, out, done, n_pairs);
    }
}

// round 14
// speedup vs baseline: 1.1948x; 1.0002x over previous
#include <cuda_runtime.h>
#include <math.h>

// Input order (metadata): 0:N 1:Zf 2:rij 3:cutoff_values 4:idx_i 5:idx_j
//                         6:adiv 7:apow 8:c1 9:c2 10:c3 11:c4 12:a1 13:a2 14:a3 15:a4
// Output: float[N]

#define KEHALF 7.199822675975274f

struct ZParams {
    float sp_adiv, sp_apow;
    float c1n, c2n, c3n, c4n;
    float s1, s2, s3, s4;
};

__device__ ZParams g_p;

// Fast float softplus (one-time scalar prep; exactness irrelevant at 1e-3 tol).
static __device__ __forceinline__ float sp_f(float x) {
    return log1pf(__expf(x));
}

// Fused: zero the output array (grid-stride float4) AND compute the derived
// scalar parameters (block 0, warp 0, parallel lanes). Triggers programmatic
// launch completion so the PDL-dependent main kernel can overlap its front end.
__global__ void zbl_zero_prep_kernel(float4* __restrict__ out4, int n4,
                                     float* __restrict__ out_tail, int tail_lo, int tail_hi,
                                     const float* adiv, const float* apow,
                                     const float* c1, const float* c2,
                                     const float* c3, const float* c4,
                                     const float* a1, const float* a2,
                                     const float* a3, const float* a4) {
    // params: block 0, warp 0
    if (blockIdx.x == 0 && threadIdx.x < 32) {
        int lane = threadIdx.x;
        const float* srcs[10] = {adiv, apow, c1, c2, c3, c4, a1, a2, a3, a4};
        float v = 0.0f;
        if (lane < 10) v = sp_f(srcs[lane][0]);
        float sp_adiv = __shfl_sync(0xffffffffu, v, 0);
        float sp_apow = __shfl_sync(0xffffffffu, v, 1);
        float c1p     = __shfl_sync(0xffffffffu, v, 2);
        float c2p     = __shfl_sync(0xffffffffu, v, 3);
        float c3p     = __shfl_sync(0xffffffffu, v, 4);
        float c4p     = __shfl_sync(0xffffffffu, v, 5);
        float s1      = __shfl_sync(0xffffffffu, v, 6);
        float s2      = __shfl_sync(0xffffffffu, v, 7);
        float s3      = __shfl_sync(0xffffffffu, v, 8);
        float s4      = __shfl_sync(0xffffffffu, v, 9);
        if (lane == 0) {
            float inv = 1.0f / (c1p + c2p + c3p + c4p);
            ZParams p;
            p.sp_adiv = sp_adiv;
            p.sp_apow = sp_apow;
            p.c1n = c1p * inv;
            p.c2n = c2p * inv;
            p.c3n = c3p * inv;
            p.c4n = c4p * inv;
            p.s1 = s1; p.s2 = s2; p.s3 = s3; p.s4 = s4;
            g_p = p;
        }
    }
    // zero
    const float4 z4 = make_float4(0.f, 0.f, 0.f, 0.f);
    for (int i = blockIdx.x * blockDim.x + threadIdx.x; i < n4;
         i += gridDim.x * blockDim.x) {
        out4[i] = z4;
    }
    // scalar tail of the zero (if out_size % 4 != 0)
    int t = tail_lo + blockIdx.x * blockDim.x + threadIdx.x;
    if (t < tail_hi) out_tail[t] = 0.0f;

    // Let the dependent kernel know our memory is (about to be) visible.
    cudaTriggerProgrammaticLaunchCompletion();
}

__device__ __forceinline__ float zbl_pair(const ZParams& p,
                                          float Zi, float Zj,
                                          float r, float cut) {
    // z = Z^sp(apow)  -> MUFU.LG2 + FMUL + MUFU.EX2
    float zi = __powf(Zi, p.sp_apow);
    float zj = __powf(Zj, p.sp_apow);
    float a  = (zi + zj) * p.sp_adiv;
    float ar = a * r;
    float f = p.c1n * __expf(-p.s1 * ar)
            + p.c2n * __expf(-p.s2 * ar)
            + p.c3n * __expf(-p.s3 * ar)
            + p.c4n * __expf(-p.s4 * ar);
    float zizj = Zi * Zj;
    return __fdividef(KEHALF * f * cut * zizj, r);
}

__global__ void __launch_bounds__(256)
zbl_pair_kernel4(const float* __restrict__ Zf,
                 const float4* __restrict__ rij4,
                 const float4* __restrict__ cut4,
                 const int4* __restrict__ ii4,
                 const int4* __restrict__ jj4,
                 float* __restrict__ out,
                 int n4) {
    int t = blockIdx.x * blockDim.x + threadIdx.x;

    float4 r, c;
    int4 ii, jj;
    float Zi[4], Zj[4];
    int ia[4], ja[4];

    bool active = (t < n4);
    if (active) {
        // All of these read only INPUT arrays — independent of the zero/prep
        // kernel, so they may issue before the PDL dependency resolves.
        r  = __ldg(&rij4[t]);
        c  = __ldg(&cut4[t]);
        ii = __ldg(&ii4[t]);
        jj = __ldg(&jj4[t]);

        ia[0] = ii.x; ia[1] = ii.y; ia[2] = ii.z; ia[3] = ii.w;
        ja[0] = jj.x; ja[1] = jj.y; ja[2] = jj.z; ja[3] = jj.w;

#pragma unroll
        for (int k = 0; k < 4; k++) {
            Zi[k] = __ldg(Zf + ia[k]);
            Zj[k] = __ldg(Zf + ja[k]);
        }
    }

    // Wait for the zero+prep kernel's memory (g_p and zeroed out[]).
    cudaGridDependencySynchronize();

    if (!active) return;

    ZParams p = g_p;

    float rr[4] = {r.x, r.y, r.z, r.w};
    float cc[4] = {c.x, c.y, c.z, c.w};

    float contrib[4];
#pragma unroll
    for (int k = 0; k < 4; k++) {
        contrib[k] = zbl_pair(p, Zi[k], Zj[k], rr[k], cc[k]);
    }

#pragma unroll
    for (int k = 0; k < 4; k++) {
        atomicAdd(out + ia[k], contrib[k]);
    }
}

__global__ void zbl_pair_tail(const float* __restrict__ Zf,
                              const float* __restrict__ rij,
                              const float* __restrict__ cut,
                              const int* __restrict__ idx_i,
                              const int* __restrict__ idx_j,
                              float* __restrict__ out,
                              int start, int n) {
    int t = start + blockIdx.x * blockDim.x + threadIdx.x;
    if (t >= n) return;
    ZParams p = g_p;
    float contrib = zbl_pair(p, __ldg(Zf + idx_i[t]), __ldg(Zf + idx_j[t]),
                             rij[t], cut[t]);
    atomicAdd(out + idx_i[t], contrib);
}

extern "C" void kernel_launch(void* const* d_in, const int* in_sizes, int n_in,
                              void* d_out, int out_size) {
    const float* Zf    = (const float*)d_in[1];
    const float* rij   = (const float*)d_in[2];
    const float* cut   = (const float*)d_in[3];
    const int*   idx_i = (const int*)d_in[4];
    const int*   idx_j = (const int*)d_in[5];
    const float* adiv  = (const float*)d_in[6];
    const float* apow  = (const float*)d_in[7];
    const float* c1    = (const float*)d_in[8];
    const float* c2    = (const float*)d_in[9];
    const float* c3    = (const float*)d_in[10];
    const float* c4    = (const float*)d_in[11];
    const float* a1    = (const float*)d_in[12];
    const float* a2    = (const float*)d_in[13];
    const float* a3    = (const float*)d_in[14];
    const float* a4    = (const float*)d_in[15];
    float* out = (float*)d_out;

    int n_pairs = in_sizes[2];

    // 1) fused zero + scalar prep (single launch)
    int o4 = out_size / 4;
    int tail_lo = o4 * 4;
    {
        int threads = 256;
        int blocks = (o4 + threads - 1) / threads;
        if (blocks < 1) blocks = 1;
        if (blocks > 1024) blocks = 1024;
        zbl_zero_prep_kernel<<<blocks, threads>>>(
            (float4*)out, o4, out, tail_lo, out_size,
            adiv, apow, c1, c2, c3, c4, a1, a2, a3, a4);
    }

    // 2) main pair sweep via PDL: starts early, syncs before atomics
    int n4 = n_pairs / 4;
    if (n4 > 0) {
        int threads = 256;
        int blocks = (n4 + threads - 1) / threads;

        cudaLaunchConfig_t cfg = {};
        cfg.gridDim = dim3((unsigned)blocks, 1, 1);
        cfg.blockDim = dim3((unsigned)threads, 1, 1);
        cfg.dynamicSmemBytes = 0;
        cfg.stream = 0;
        cudaLaunchAttribute attrs[1];
        attrs[0].id = cudaLaunchAttributeProgrammaticStreamSerialization;
        attrs[0].val.programmaticStreamSerializationAllowed = 1;
        cfg.attrs = attrs;
        cfg.numAttrs = 1;

        cudaLaunchKernelEx(&cfg, zbl_pair_kernel4,
                           Zf, (const float4*)rij, (const float4*)cut,
                           (const int4*)idx_i, (const int4*)idx_j, out, n4);
    }

    // 3) tail (n_pairs not divisible by 4)
    int done = n4 * 4;
    int rem = n_pairs - done;
    if (rem > 0) {
        zbl_pair_tail<<<(rem + 255) / 256, 256>>>(
            Zf, rij, cut, idx_i, idx_j, out, done, n_pairs);
    }
}